// round 2
// baseline (speedup 1.0000x reference)
#include <cuda_runtime.h>

#define NSAMP  2048            // 32 * 64
#define IMG    512
#define NCHAN  3
#define NTERMS (NSAMP * NCHAN) // 6144
#define ROWS   8               // window rows per term
#define TPB    256
#define NBLOCKS ((NTERMS * ROWS) / TPB)   // 192

__device__ float        g_acc;   // zero-init; reset by last block each run
__device__ unsigned int g_cnt;

// numpy 'reflect' (edge not repeated): -1 -> 1, 512 -> 510
__device__ __forceinline__ int reflect_idx(int t) {
    t = (t < 0) ? -t : t;
    t = (t >= IMG) ? (2 * IMG - 2 - t) : t;
    return t;
}

__global__ __launch_bounds__(TPB)
void color_loss_kernel(const float* __restrict__ pred,   // [32,64,8]
                       const float* __restrict__ img,    // [32,3,512,512]
                       float* __restrict__ out)
{
    const float kk[7] = {
        0.0044330481752437470f, 0.0540055826225118500f, 0.2420362293759061000f,
        0.3990502796524549000f,
        0.2420362293759061000f, 0.0540055826225118500f, 0.0044330481752437470f
    };

    const int gid  = blockIdx.x * TPB + threadIdx.x;
    const int term = gid >> 3;       // (sample, channel) index, 0..6143 (exact grid)
    const int row  = gid & 7;        // window row 0..7

    const int s = term / NCHAN;
    const int c = term - s * NCHAN;
    const int b = s >> 6;

    const float* p = pred + (size_t)s * 8;
    const float px  = p[0];
    const float py  = p[1];
    const float col = p[5 + c];

    // exact reference arithmetic chain (fp32 rounding preserved)
    const float gx = 2.0f * px - 1.0f;
    const float gy = 2.0f * py - 1.0f;
    float x = ((gx + 1.0f) * (float)IMG - 1.0f) * 0.5f;
    float y = ((gy + 1.0f) * (float)IMG - 1.0f) * 0.5f;
    x = fminf(fmaxf(x, 0.0f), (float)(IMG - 1));
    y = fminf(fmaxf(y, 0.0f), (float)(IMG - 1));

    const float x0f = floorf(x);
    const float y0f = floorf(y);
    const float wx = x - x0f;
    const float wy = y - y0f;
    const int x0 = (int)x0f;
    const int y0 = (int)y0f;
    const bool xs = (x0 + 1 <= IMG - 1);
    const bool ys = (y0 + 1 <= IMG - 1);

    const float* base = img + ((size_t)b * NCHAN + c) * (size_t)(IMG * IMG);
    const int ry = reflect_idx(y0 - 3 + row);
    const float* rowp = base + (size_t)ry * IMG;

    // 8 columns of this row (reflect at borders; interior = contiguous)
    int cx[8];
    #pragma unroll
    for (int j = 0; j < 8; j++) cx[j] = reflect_idx(x0 - 3 + j);

    float pv[8];
    #pragma unroll
    for (int j = 0; j < 8; j++) pv[j] = __ldg(&rowp[cx[j]]);

    // horizontal blur at shift 0 and shift +1
    float h0 = 0.0f, hsh = 0.0f;
    #pragma unroll
    for (int j = 0; j < 7; j++) {
        h0  += kk[j] * pv[j];
        hsh += kk[j] * pv[j + 1];
    }
    const float h1 = xs ? hsh : h0;

    // vertical weights for shift-0 (rows 0..6) and shift-1 (rows 1..7)
    const float wv0 = (row < 7) ? kk[row]     : 0.0f;
    const float wv1 = (row > 0) ? kk[row - 1] : 0.0f;
    float v00  = wv0 * h0;
    float v01  = wv0 * h1;
    float v00s = wv1 * h0;
    float v01s = wv1 * h1;

    // sum across the 8 lanes of this term (lanes are 8-aligned groups)
    #pragma unroll
    for (int o = 1; o < 8; o <<= 1) {
        v00  += __shfl_xor_sync(0xffffffffu, v00,  o);
        v01  += __shfl_xor_sync(0xffffffffu, v01,  o);
        v00s += __shfl_xor_sync(0xffffffffu, v00s, o);
        v01s += __shfl_xor_sync(0xffffffffu, v01s, o);
    }

    float local = 0.0f;
    if (row == 0) {
        const float v10 = ys ? v00s : v00;
        const float v11 = ys ? v01s : v01;
        const float target = v00 * (1.0f - wx) * (1.0f - wy)
                           + v01 * wx          * (1.0f - wy)
                           + v10 * (1.0f - wx) * wy
                           + v11 * wx          * wy;
        const float d = col - target;
        local = d * d * (1.0f / (float)NTERMS);
    }

    // warp reduce
    #pragma unroll
    for (int o = 16; o > 0; o >>= 1)
        local += __shfl_down_sync(0xffffffffu, local, o);

    __shared__ float ws[TPB / 32];
    const int lane = threadIdx.x & 31;
    const int wid  = threadIdx.x >> 5;
    if (lane == 0) ws[wid] = local;
    __syncthreads();

    if (threadIdx.x == 0) {
        float bsum = 0.0f;
        #pragma unroll
        for (int w = 0; w < TPB / 32; w++) bsum += ws[w];

        atomicAdd(&g_acc, bsum);
        __threadfence();
        const unsigned int done = atomicAdd(&g_cnt, 1u);
        if (done == (unsigned int)(NBLOCKS - 1)) {
            // last block: publish result, reset state for next graph replay
            const float total = atomicAdd(&g_acc, 0.0f);  // acquire-ish read
            out[0] = total;
            g_acc = 0.0f;
            g_cnt = 0u;
            __threadfence();
        }
    }
}

extern "C" void kernel_launch(void* const* d_in, const int* in_sizes, int n_in,
                              void* d_out, int out_size) {
    const float* pred = (const float*)d_in[0];
    const float* img  = (const float*)d_in[1];
    if (n_in >= 2 && in_sizes[0] != NSAMP * 8) {   // defensive input-order check
        pred = (const float*)d_in[1];
        img  = (const float*)d_in[0];
    }
    float* out = (float*)d_out;

    color_loss_kernel<<<NBLOCKS, TPB>>>(pred, img, out);
}